// round 5
// baseline (speedup 1.0000x reference)
#include <cuda_runtime.h>
#include <cuda_bf16.h>
#include <cstdint>
#include <math_constants.h>

#define NN 256          // NUM_NEURONS
#define NS 512          // NUM_SAMPLES
#define MAXSP 32        // MAX_SPIKES (rounds)
#define NSTEPS 32       // RK4 steps per round
#define V_RESET 1.0f

__device__ __forceinline__ float fast_sigmoid(float v) {
    return 1.0f / (1.0f + __expf(-v));
}

// Linear RK4 propagation for (v, i): dv = mu1*(i + c - v), di = -mu2*i.
__device__ __forceinline__ void lin_rk4(float v, float i, float c,
                                        float h, float mu1, float mu2,
                                        float& v2, float& v3, float& v4,
                                        float& vn, float& in_) {
    float k1v = mu1 * (i + c - v);
    float k1i = -mu2 * i;
    float v2_ = v + 0.5f * h * k1v;
    float i2  = i + 0.5f * h * k1i;
    float k2v = mu1 * (i2 + c - v2_);
    float k2i = -mu2 * i2;
    float v3_ = v + 0.5f * h * k2v;
    float i3  = i + 0.5f * h * k2i;
    float k3v = mu1 * (i3 + c - v3_);
    float k3i = -mu2 * i3;
    float v4_ = v + h * k3v;
    float i4  = i + h * k3i;
    float k4v = mu1 * (i4 + c - v4_);
    float k4i = -mu2 * i4;
    float c6 = h * (1.0f / 6.0f);
    vn  = v + c6 * (k1v + 2.0f * k2v + 2.0f * k3v + k4v);
    in_ = i + c6 * (k1i + 2.0f * k2i + 2.0f * k3i + k4i);
    v2 = v2_; v3 = v3_; v4 = v4_;
}

struct Coef {
    float A2, A3, A4, An;
    float B2, B3, B4, Bn, Pn;
    float c2, c3, c4, cn, c6;
};

__device__ __forceinline__ void do_step(const Coef& C, float v, float i, float s,
                                        float& vn, float& in_, float& sn) {
    const float v2 = fmaf(C.A2, v, fmaf(C.B2, i, C.c2));
    const float v3 = fmaf(C.A3, v, fmaf(C.B3, i, C.c3));
    const float v4 = fmaf(C.A4, v, fmaf(C.B4, i, C.c4));
    vn  = fmaf(C.An, v, fmaf(C.Bn, i, C.cn));
    in_ = C.Pn * i;
    const float ds = fast_sigmoid(v)
                   + 2.0f * (fast_sigmoid(v2) + fast_sigmoid(v3))
                   + fast_sigmoid(v4);
    sn = fmaf(C.c6, ds, s);
}

// order-preserving float->uint map (handles negatives)
__device__ __forceinline__ unsigned f2ord(float x) {
    unsigned u = __float_as_uint(x);
    return (u & 0x80000000u) ? ~u : (u | 0x80000000u);
}

__global__ __launch_bounds__(NN, 8)
void snn_kernel(const float* __restrict__ ic_g,     // [NN]
                const float* __restrict__ w,        // [NN, NN]
                const float* __restrict__ mu_g,     // [2]
                const float* __restrict__ v0_g,     // [NN]
                const float* __restrict__ i0_g,     // [NN]
                const float* __restrict__ s0_g,     // [NS, NN]
                const float* __restrict__ reset_s,  // [MAXSP, NS, NN]
                const int*   __restrict__ t1_p,     // scalar
                float* __restrict__ out_times,      // [NS, MAXSP]
                float* __restrict__ out_vals,       // [NS, MAXSP, NN, 3]
                float* __restrict__ out_marks)      // [NS, MAXSP, NN]
{
    const int smp = blockIdx.x;
    const int n   = threadIdx.x;
    const int warp = n >> 5, lane = n & 31;

    const float t1f = (float)(*t1_p);
    const float mu1 = mu_g[0];
    const float mu2 = mu_g[1];
    const float ic  = ic_g[n];

    float v = v0_g[n];
    float i = i0_g[n];
    float s = s0_g[(size_t)smp * NN + n];
    float t0 = 0.0f;

    __shared__ int      c_st[8];
    __shared__ float    c_sn[8];
    __shared__ float    c_sp[8];
    __shared__ int      c_idx[8];
    __shared__ unsigned ballots[8];

    #pragma unroll 1
    for (int k = 0; k < MAXSP; k++) {
        const float rs = reset_s[((size_t)k * NS + smp) * NN + n];

        const float dt = (t1f - t0) * (1.0f / NSTEPS);
        bool  done = false;
        float tev  = t1f;
        bool  em   = false;
        int   eidx = 0;

        if (dt > 0.0f) {
            // ---- per-round linear RK4 coefficients ----
            Coef C;
            {
                float d0, d1, Cc2, Cc3, Cc4, Ccn;
                lin_rk4(1.f, 0.f, 0.f, dt, mu1, mu2, C.A2, C.A3, C.A4, C.An, d0);
                lin_rk4(0.f, 1.f, 0.f, dt, mu1, mu2, C.B2, C.B3, C.B4, C.Bn, C.Pn);
                lin_rk4(0.f, 0.f, 1.f, dt, mu1, mu2, Cc2, Cc3, Cc4, Ccn, d1);
                C.c2 = Cc2 * ic; C.c3 = Cc3 * ic; C.c4 = Cc4 * ic; C.cn = Ccn * ic;
                C.c6 = dt * (1.0f / 6.0f);
            }

            // round-start state (for recompute)
            const float vr = v, ir = i, sr = s;

            // ---- warp-autonomous scan: no block syncs ----
            int   wst = NSTEPS + 1;
            float wsn = 0.0f, wsp = 0.0f;
            int   widx = 0;

            #pragma unroll 1
            for (int st = 1; st <= NSTEPS; st++) {
                float vn, in_, sn;
                do_step(C, v, i, s, vn, in_, sn);
                unsigned cr = __ballot_sync(0xffffffffu, sn > 0.0f);
                if (cr) {
                    // warp argmax of sn (tie -> lowest lane), packed 64-bit
                    unsigned long long key =
                        ((unsigned long long)f2ord(sn) << 8) | (unsigned)(31 - lane);
                    #pragma unroll
                    for (int off = 16; off; off >>= 1) {
                        unsigned long long ok = __shfl_xor_sync(0xffffffffu, key, off);
                        key = (ok > key) ? ok : key;
                    }
                    const int wl = 31 - (int)(key & 0xffu);
                    wsn  = __shfl_sync(0xffffffffu, sn, wl);
                    wsp  = __shfl_sync(0xffffffffu, s,  wl);
                    widx = warp * 32 + wl;
                    wst  = st;
                    break;
                }
                v = vn; i = in_; s = sn;
            }

            // ---- block combine (barrier #1) ----
            if (lane == 0) {
                c_st[warp] = wst; c_sn[warp] = wsn;
                c_sp[warp] = wsp; c_idx[warp] = widx;
            }
            __syncthreads();
            int mst = c_st[0]; float mval = c_sn[0]; float msp = c_sp[0]; int midx = c_idx[0];
            #pragma unroll
            for (int wv = 1; wv < 8; wv++) {
                const int ost = c_st[wv]; const float osn = c_sn[wv]; const int oidx = c_idx[wv];
                const bool better = (ost < mst) ||
                                    (ost == mst && (osn > mval ||
                                                    (osn == mval && oidx < midx)));
                if (better) { mst = ost; mval = osn; msp = c_sp[wv]; midx = oidx; }
            }

            if (mst <= NSTEPS) {
                // ---- recompute mst steps from round start (mst is small) ----
                float tt = t0;
                v = vr; i = ir; s = sr;
                float vn, in_, sn;
                #pragma unroll 1
                for (int m = 1; m <= mst; m++) {
                    do_step(C, v, i, s, vn, in_, sn);
                    if (m < mst) { v = vn; i = in_; s = sn; tt += dt; }
                }
                float frac = msp / (msp - mval + 1e-12f);
                frac = fminf(fmaxf(frac, 0.0f), 1.0f);
                tev = tt + frac * dt;
                em  = (n == midx) || (sn > 0.0f);
                v += frac * (vn - v);
                i += frac * (in_ - i);
                s += frac * (sn - s);
                done = true;

                // ---- eidx = first neuron with emask (barrier #2) ----
                unsigned b = __ballot_sync(0xffffffffu, em);
                if (lane == 0) ballots[warp] = b;
                __syncthreads();
                #pragma unroll
                for (int wv = 0; wv < 8; wv++) {
                    unsigned bb = ballots[wv];
                    if (bb) { eidx = wv * 32 + (__ffs(bb) - 1); break; }
                }
            } else {
                // no trigger: state already holds y(32). Barrier protects cand
                // arrays before next round's writes.
                __syncthreads();
            }
        }

        // ---- outputs (pre-reset event state); tev = t1f if no trigger ----
        const size_t base = ((size_t)smp * MAXSP + k) * NN + n;
        if (n == 0) out_times[smp * MAXSP + k] = tev;
        out_vals[base * 3 + 0] = v;
        out_vals[base * 3 + 1] = i;
        out_vals[base * 3 + 2] = s;
        out_marks[base] = em ? 1.0f : 0.0f;

        // ---- reset & carry ----
        const float wr = done ? w[(size_t)eidx * NN + n] : 0.0f;
        v -= em ? V_RESET : 0.0f;
        i += wr;
        s  = fminf(em ? rs : s, 0.0f);
        t0 = tev;
    }
}

extern "C" void kernel_launch(void* const* d_in, const int* in_sizes, int n_in,
                              void* d_out, int out_size) {
    const float* ic      = (const float*)d_in[0];
    const float* w       = (const float*)d_in[1];
    const float* mu      = (const float*)d_in[2];
    const float* v0      = (const float*)d_in[3];
    const float* i0      = (const float*)d_in[4];
    const float* s0      = (const float*)d_in[5];
    const float* reset_s = (const float*)d_in[6];
    const int*   t1      = (const int*)d_in[7];

    float* out = (float*)d_out;
    float* out_times = out;                                    // NS*MAXSP
    float* out_vals  = out + (size_t)NS * MAXSP;               // NS*MAXSP*NN*3
    float* out_marks = out_vals + (size_t)NS * MAXSP * NN * 3; // NS*MAXSP*NN

    snn_kernel<<<NS, NN>>>(ic, w, mu, v0, i0, s0, reset_s, t1,
                           out_times, out_vals, out_marks);
}

// round 6
// speedup vs baseline: 1.1291x; 1.1291x over previous
#include <cuda_runtime.h>
#include <cuda_bf16.h>
#include <cstdint>
#include <math_constants.h>

#define NN 256          // NUM_NEURONS
#define NS 512          // NUM_SAMPLES
#define MAXSP 32        // MAX_SPIKES (rounds)
#define NSTEPS 32       // RK4 steps per round
#define CH 4            // steps per chunk
#define NCHUNK (NSTEPS / CH)
#define V_RESET 1.0f

__device__ __forceinline__ float fast_sigmoid(float v) {
    return 1.0f / (1.0f + __expf(-v));
}

// Linear RK4 propagation for (v, i): dv = mu1*(i + c - v), di = -mu2*i.
__device__ __forceinline__ void lin_rk4(float v, float i, float c,
                                        float h, float mu1, float mu2,
                                        float& v2, float& v3, float& v4,
                                        float& vn, float& in_) {
    float k1v = mu1 * (i + c - v);
    float k1i = -mu2 * i;
    float v2_ = v + 0.5f * h * k1v;
    float i2  = i + 0.5f * h * k1i;
    float k2v = mu1 * (i2 + c - v2_);
    float k2i = -mu2 * i2;
    float v3_ = v + 0.5f * h * k2v;
    float i3  = i + 0.5f * h * k2i;
    float k3v = mu1 * (i3 + c - v3_);
    float k3i = -mu2 * i3;
    float v4_ = v + h * k3v;
    float i4  = i + h * k3i;
    float k4v = mu1 * (i4 + c - v4_);
    float k4i = -mu2 * i4;
    float c6 = h * (1.0f / 6.0f);
    vn  = v + c6 * (k1v + 2.0f * k2v + 2.0f * k3v + k4v);
    in_ = i + c6 * (k1i + 2.0f * k2i + 2.0f * k3i + k4i);
    v2 = v2_; v3 = v3_; v4 = v4_;
}

struct Coef {
    float A2, A3, A4, An;
    float B2, B3, B4, Bn, Pn;
    float c2, c3, c4, cn, c6;
};

__device__ __forceinline__ void do_step(const Coef& C, float v, float i, float s,
                                        float& vn, float& in_, float& sn) {
    const float v2 = fmaf(C.A2, v, fmaf(C.B2, i, C.c2));
    const float v3 = fmaf(C.A3, v, fmaf(C.B3, i, C.c3));
    const float v4 = fmaf(C.A4, v, fmaf(C.B4, i, C.c4));
    vn  = fmaf(C.An, v, fmaf(C.Bn, i, C.cn));
    in_ = C.Pn * i;
    const float ds = fast_sigmoid(v)
                   + 2.0f * (fast_sigmoid(v2) + fast_sigmoid(v3))
                   + fast_sigmoid(v4);
    sn = fmaf(C.c6, ds, s);
}

// order-preserving float<->uint maps
__device__ __forceinline__ unsigned f2ord(float x) {
    unsigned u = __float_as_uint(x);
    return (u & 0x80000000u) ? ~u : (u | 0x80000000u);
}
__device__ __forceinline__ float ord2f(unsigned o) {
    unsigned u = (o & 0x80000000u) ? (o & 0x7fffffffu) : ~o;
    return __uint_as_float(u);
}

__global__ __launch_bounds__(NN, 4)
void snn_kernel(const float* __restrict__ ic_g,     // [NN]
                const float* __restrict__ w,        // [NN, NN]
                const float* __restrict__ mu_g,     // [2]
                const float* __restrict__ v0_g,     // [NN]
                const float* __restrict__ i0_g,     // [NN]
                const float* __restrict__ s0_g,     // [NS, NN]
                const float* __restrict__ reset_s,  // [MAXSP, NS, NN]
                const int*   __restrict__ t1_p,     // scalar
                float* __restrict__ out_times,      // [NS, MAXSP]
                float* __restrict__ out_vals,       // [NS, MAXSP, NN, 3]
                float* __restrict__ out_marks)      // [NS, MAXSP, NN]
{
    const int smp = blockIdx.x;
    const int n   = threadIdx.x;
    const int warp = n >> 5, lane = n & 31;

    const float t1f = (float)(*t1_p);
    const float mu1 = mu_g[0];
    const float mu2 = mu_g[1];
    const float ic  = ic_g[n];

    float v = v0_g[n];
    float i = i0_g[n];
    float s = s0_g[(size_t)smp * NN + n];
    float t0 = 0.0f;

    __shared__ int                c_mf[NCHUNK][8];   // per-chunk per-warp first step
    __shared__ unsigned long long c_key[8];
    __shared__ float              c_sp[8];
    __shared__ unsigned           c_bal[8];

    #pragma unroll 1
    for (int k = 0; k < MAXSP; k++) {
        const float rs = reset_s[((size_t)k * NS + smp) * NN + n];

        const float dt = (t1f - t0) * (1.0f / NSTEPS);
        bool  done = false;
        float tev  = t1f;
        bool  em   = false;
        int   eidx = 0;

        if (dt > 0.0f) {
            // ---- per-round linear RK4 coefficients ----
            Coef C;
            {
                float d0, d1, Cc2, Cc3, Cc4, Ccn;
                lin_rk4(1.f, 0.f, 0.f, dt, mu1, mu2, C.A2, C.A3, C.A4, C.An, d0);
                lin_rk4(0.f, 1.f, 0.f, dt, mu1, mu2, C.B2, C.B3, C.B4, C.Bn, C.Pn);
                lin_rk4(0.f, 0.f, 1.f, dt, mu1, mu2, Cc2, Cc3, Cc4, Ccn, d1);
                C.c2 = Cc2 * ic; C.c3 = Cc3 * ic; C.c4 = Cc4 * ic; C.cn = Ccn * ic;
                C.c6 = dt * (1.0f / 6.0f);
            }

            float v_h[CH + 1], i_h[CH + 1], s_h[CH + 1];
            int gst = CH + 1;
            int st_base = 0;

            // ---- chunked scan: 1 barrier per 4 steps ----
            #pragma unroll 1
            for (int ch = 0; ch < NCHUNK; ch++) {
                v_h[0] = v; i_h[0] = i; s_h[0] = s;
                unsigned bl[CH];
                #pragma unroll
                for (int j = 1; j <= CH; j++) {
                    do_step(C, v_h[j-1], i_h[j-1], s_h[j-1],
                            v_h[j], i_h[j], s_h[j]);
                    bl[j-1] = __ballot_sync(0xffffffffu, s_h[j] > 0.0f);
                }
                const int wmf = bl[0] ? 1 : (bl[1] ? 2 : (bl[2] ? 3 : (bl[3] ? 4 : CH + 1)));
                if (lane == 0) c_mf[ch][warp] = wmf;
                __syncthreads();
                gst = c_mf[ch][0];
                #pragma unroll
                for (int wv = 1; wv < 8; wv++) gst = min(gst, c_mf[ch][wv]);
                if (gst <= CH) break;   // trigger in this chunk (block-uniform)
                v = v_h[CH]; i = i_h[CH]; s = s_h[CH];
                st_base += CH;
            }

            if (gst <= CH) {
                // ---- event processing (once per round) ----
                float sn_t = s_h[1], sp_t = s_h[0];
                float vn_t = v_h[1], vp_t = v_h[0];
                float in_t = i_h[1], ip_t = i_h[0];
                #pragma unroll
                for (int j = 2; j <= CH; j++) {
                    if (gst == j) {
                        sn_t = s_h[j]; sp_t = s_h[j-1];
                        vn_t = v_h[j]; vp_t = v_h[j-1];
                        in_t = i_h[j]; ip_t = i_h[j-1];
                    }
                }
                em = sn_t > 0.0f;

                // warp argmax: key = (ord(sn), 255 - n) -> max = max sn, tie min n
                unsigned long long key =
                    ((unsigned long long)f2ord(sn_t) << 8) | (unsigned)(255 - n);
                #pragma unroll
                for (int off = 16; off; off >>= 1) {
                    unsigned long long ok = __shfl_xor_sync(0xffffffffu, key, off);
                    key = (ok > key) ? ok : key;
                }
                const int wl = (255 - (int)(key & 0xffu)) & 31;
                const float wsp = __shfl_sync(0xffffffffu, sp_t, wl);
                const unsigned b = __ballot_sync(0xffffffffu, em);
                if (lane == 0) { c_key[warp] = key; c_sp[warp] = wsp; c_bal[warp] = b; }
                __syncthreads();

                unsigned long long mkey = c_key[0]; float msp = c_sp[0];
                #pragma unroll
                for (int wv = 1; wv < 8; wv++)
                    if (c_key[wv] > mkey) { mkey = c_key[wv]; msp = c_sp[wv]; }
                const float mval = ord2f((unsigned)(mkey >> 8));

                #pragma unroll
                for (int wv = 0; wv < 8; wv++) {
                    unsigned bb = c_bal[wv];
                    if (bb) { eidx = wv * 32 + (__ffs(bb) - 1); break; }
                }

                float frac = msp / (msp - mval + 1e-12f);
                frac = fminf(fmaxf(frac, 0.0f), 1.0f);
                tev = t0 + (float)(st_base + gst - 1) * dt + frac * dt;
                v = vp_t + frac * (vn_t - vp_t);
                i = ip_t + frac * (in_t - ip_t);
                s = sp_t + frac * (sn_t - sp_t);
                done = true;
            }
            // else: no trigger, (v,i,s) already = y(32), tev = t1f
        }

        // ---- outputs (pre-reset event state) ----
        const size_t base = ((size_t)smp * MAXSP + k) * NN + n;
        if (n == 0) out_times[smp * MAXSP + k] = tev;
        out_vals[base * 3 + 0] = v;
        out_vals[base * 3 + 1] = i;
        out_vals[base * 3 + 2] = s;
        out_marks[base] = em ? 1.0f : 0.0f;

        // ---- reset & carry ----
        const float wr = done ? w[(size_t)eidx * NN + n] : 0.0f;
        v -= em ? V_RESET : 0.0f;
        i += wr;
        s  = fminf(em ? rs : s, 0.0f);
        t0 = tev;
    }
}

extern "C" void kernel_launch(void* const* d_in, const int* in_sizes, int n_in,
                              void* d_out, int out_size) {
    const float* ic      = (const float*)d_in[0];
    const float* w       = (const float*)d_in[1];
    const float* mu      = (const float*)d_in[2];
    const float* v0      = (const float*)d_in[3];
    const float* i0      = (const float*)d_in[4];
    const float* s0      = (const float*)d_in[5];
    const float* reset_s = (const float*)d_in[6];
    const int*   t1      = (const int*)d_in[7];

    float* out = (float*)d_out;
    float* out_times = out;                                    // NS*MAXSP
    float* out_vals  = out + (size_t)NS * MAXSP;               // NS*MAXSP*NN*3
    float* out_marks = out_vals + (size_t)NS * MAXSP * NN * 3; // NS*MAXSP*NN

    snn_kernel<<<NS, NN>>>(ic, w, mu, v0, i0, s0, reset_s, t1,
                           out_times, out_vals, out_marks);
}

// round 9
// speedup vs baseline: 2.0405x; 1.8073x over previous
#include <cuda_runtime.h>
#include <cuda_bf16.h>
#include <cstdint>

#define NN 256          // NUM_NEURONS
#define NS 512          // NUM_SAMPLES
#define MAXSP 32        // MAX_SPIKES (rounds)
#define NSTEPS 32       // RK4 steps per round
#define V_RESET 1.0f

__device__ __forceinline__ float sigm(float v) {
    const float e = __expf(-v);
    return __fdividef(1.0f, 1.0f + e);   // MUFU.RCP path, no slow DIV
}

__device__ __forceinline__ void rk4_step(float v, float i, float s,
                                         float ic, float mu1, float mu2, float h,
                                         float& vn, float& in_, float& sn) {
    // k1
    float dv1 = mu1 * (i + ic - v);
    float di1 = -mu2 * i;
    float ds1 = sigm(v);
    // k2
    float v2 = fmaf(0.5f * h, dv1, v);
    float i2 = fmaf(0.5f * h, di1, i);
    float dv2 = mu1 * (i2 + ic - v2);
    float di2 = -mu2 * i2;
    float ds2 = sigm(v2);
    // k3
    float v3 = fmaf(0.5f * h, dv2, v);
    float i3 = fmaf(0.5f * h, di2, i);
    float dv3 = mu1 * (i3 + ic - v3);
    float di3 = -mu2 * i3;
    float ds3 = sigm(v3);
    // k4
    float v4 = fmaf(h, dv3, v);
    float i4 = fmaf(h, di3, i);
    float dv4 = mu1 * (i4 + ic - v4);
    float di4 = -mu2 * i4;
    float ds4 = sigm(v4);

    const float c = h * (1.0f / 6.0f);
    vn  = fmaf(c, dv1 + 2.0f * (dv2 + dv3) + dv4, v);
    in_ = fmaf(c, di1 + 2.0f * (di2 + di3) + di4, i);
    sn  = fmaf(c, ds1 + 2.0f * (ds2 + ds3) + ds4, s);
}

// order-preserving float<->uint maps
__device__ __forceinline__ unsigned f2ord(float x) {
    unsigned u = __float_as_uint(x);
    return (u & 0x80000000u) ? ~u : (u | 0x80000000u);
}
__device__ __forceinline__ float ord2f(unsigned o) {
    unsigned u = (o & 0x80000000u) ? (o & 0x7fffffffu) : ~o;
    return __uint_as_float(u);
}

__global__ __launch_bounds__(NN, 4)
void snn_kernel(const float* __restrict__ ic_g,     // [NN]
                const float* __restrict__ w,        // [NN, NN]
                const float* __restrict__ mu_g,     // [2]
                const float* __restrict__ v0_g,     // [NN]
                const float* __restrict__ i0_g,     // [NN]
                const float* __restrict__ s0_g,     // [NS, NN]
                const float* __restrict__ reset_s,  // [MAXSP, NS, NN]
                const int*   __restrict__ t1_p,     // scalar
                float* __restrict__ out_times,      // [NS, MAXSP]
                float* __restrict__ out_vals,       // [NS, MAXSP, NN, 3]
                float* __restrict__ out_marks)      // [NS, MAXSP, NN]
{
    const int smp = blockIdx.x;
    const int n   = threadIdx.x;
    const int warp = n >> 5, lane = n & 31;

    const float t1f = (float)(*t1_p);
    const float mu1 = mu_g[0];
    const float mu2 = mu_g[1];
    const float ic  = ic_g[n];

    float v = v0_g[n];
    float i = i0_g[n];
    float s = s0_g[(size_t)smp * NN + n];
    float t0 = 0.0f;

    __shared__ float              red[2][8];  // parity double-buffered block max
    __shared__ unsigned long long c_key[8];
    __shared__ float              c_sp[8];
    __shared__ unsigned           c_bal[8];

    int chk = 0;  // checked-step counter (block-uniform) -> reduce-buffer parity

    #pragma unroll 1
    for (int k = 0; k < MAXSP; k++) {
        const float rs = reset_s[((size_t)k * NS + smp) * NN + n];

        const float dt = (t1f - t0) * (1.0f / NSTEPS);
        bool  done = false;
        float tev  = t1f;
        bool  em   = false;
        int   eidx = 0;

        if (dt > 0.0f) {
            float t = t0;
            #pragma unroll 1
            for (int st = 0; st < NSTEPS; st++) {
                float vn, in_, sn;
                rk4_step(v, i, s, ic, mu1, mu2, dt, vn, in_, sn);

                // ---- fast path: block MAX only, 1 barrier ----
                float m = sn;
                #pragma unroll
                for (int off = 16; off; off >>= 1)
                    m = fmaxf(m, __shfl_xor_sync(0xffffffffu, m, off));
                const int p = chk & 1;
                chk++;
                if (lane == 0) red[p][warp] = m;
                __syncthreads();
                float bm = red[p][0];
                #pragma unroll
                for (int wv = 1; wv < 8; wv++) bm = fmaxf(bm, red[p][wv]);

                if (bm > 0.0f) {
                    // ---- trigger (once per round): argmax + eidx, 1 barrier ----
                    em = sn > 0.0f;
                    unsigned long long key =
                        ((unsigned long long)f2ord(sn) << 8) | (unsigned)(255 - n);
                    #pragma unroll
                    for (int off = 16; off; off >>= 1) {
                        unsigned long long ok = __shfl_xor_sync(0xffffffffu, key, off);
                        key = (ok > key) ? ok : key;
                    }
                    const int wl = ((int)(255 - (key & 0xffu))) & 31;  // winner lane
                    const float wsp = __shfl_sync(0xffffffffu, s, wl); // its s_prev
                    const unsigned b = __ballot_sync(0xffffffffu, em);
                    if (lane == 0) { c_key[warp] = key; c_sp[warp] = wsp; c_bal[warp] = b; }
                    __syncthreads();

                    unsigned long long mkey = c_key[0]; float msp = c_sp[0];
                    #pragma unroll
                    for (int wv = 1; wv < 8; wv++)
                        if (c_key[wv] > mkey) { mkey = c_key[wv]; msp = c_sp[wv]; }
                    const float mval = ord2f((unsigned)(mkey >> 8));

                    #pragma unroll
                    for (int wv = 0; wv < 8; wv++) {
                        unsigned bb = c_bal[wv];
                        if (bb) { eidx = wv * 32 + (__ffs(bb) - 1); break; }
                    }

                    float frac = msp / (msp - mval + 1e-12f);
                    frac = fminf(fmaxf(frac, 0.0f), 1.0f);
                    tev = t + frac * dt;
                    v += frac * (vn - v);
                    i += frac * (in_ - i);
                    s += frac * (sn - s);
                    done = true;
                    break;
                }
                v = vn; i = in_; s = sn;
                t += dt;
            }
        }

        // ---- outputs (pre-reset event state); tev = t1f if no trigger ----
        const size_t base = ((size_t)smp * MAXSP + k) * NN + n;
        if (n == 0) out_times[smp * MAXSP + k] = tev;
        out_vals[base * 3 + 0] = v;
        out_vals[base * 3 + 1] = i;
        out_vals[base * 3 + 2] = s;
        out_marks[base] = em ? 1.0f : 0.0f;

        // ---- reset & carry ----
        const float wr = done ? w[(size_t)eidx * NN + n] : 0.0f;
        v -= em ? V_RESET : 0.0f;
        i += wr;
        s  = fminf(em ? rs : s, 0.0f);
        t0 = tev;
    }
}

extern "C" void kernel_launch(void* const* d_in, const int* in_sizes, int n_in,
                              void* d_out, int out_size) {
    const float* ic      = (const float*)d_in[0];
    const float* w       = (const float*)d_in[1];
    const float* mu      = (const float*)d_in[2];
    const float* v0      = (const float*)d_in[3];
    const float* i0      = (const float*)d_in[4];
    const float* s0      = (const float*)d_in[5];
    const float* reset_s = (const float*)d_in[6];
    const int*   t1      = (const int*)d_in[7];

    float* out = (float*)d_out;
    float* out_times = out;                                    // NS*MAXSP
    float* out_vals  = out + (size_t)NS * MAXSP;               // NS*MAXSP*NN*3
    float* out_marks = out_vals + (size_t)NS * MAXSP * NN * 3; // NS*MAXSP*NN

    snn_kernel<<<NS, NN>>>(ic, w, mu, v0, i0, s0, reset_s, t1,
                           out_times, out_vals, out_marks);
}

// round 10
// speedup vs baseline: 2.1738x; 1.0653x over previous
#include <cuda_runtime.h>
#include <cuda_bf16.h>
#include <cstdint>

#define NN 256          // NUM_NEURONS
#define NS 512          // NUM_SAMPLES
#define MAXSP 32        // MAX_SPIKES (rounds)
#define NSTEPS 32       // RK4 steps per round
#define V_RESET 1.0f

__device__ __forceinline__ float sigm(float v) {
    const float e = __expf(-v);
    return __fdividef(1.0f, 1.0f + e);   // MUFU.EX2 + MUFU.RCP path
}

__device__ __forceinline__ void rk4_step(float v, float i, float s,
                                         float ic, float mu1, float mu2, float h,
                                         float& vn, float& in_, float& sn) {
    // k1
    float dv1 = mu1 * (i + ic - v);
    float di1 = -mu2 * i;
    float ds1 = sigm(v);
    // k2
    float v2 = fmaf(0.5f * h, dv1, v);
    float i2 = fmaf(0.5f * h, di1, i);
    float dv2 = mu1 * (i2 + ic - v2);
    float di2 = -mu2 * i2;
    float ds2 = sigm(v2);
    // k3
    float v3 = fmaf(0.5f * h, dv2, v);
    float i3 = fmaf(0.5f * h, di2, i);
    float dv3 = mu1 * (i3 + ic - v3);
    float di3 = -mu2 * i3;
    float ds3 = sigm(v3);
    // k4
    float v4 = fmaf(h, dv3, v);
    float i4 = fmaf(h, di3, i);
    float dv4 = mu1 * (i4 + ic - v4);
    float di4 = -mu2 * i4;
    float ds4 = sigm(v4);

    const float c = h * (1.0f / 6.0f);
    vn  = fmaf(c, dv1 + 2.0f * (dv2 + dv3) + dv4, v);
    in_ = fmaf(c, di1 + 2.0f * (di2 + di3) + di4, i);
    sn  = fmaf(c, ds1 + 2.0f * (ds2 + ds3) + ds4, s);
}

// order-preserving float<->uint maps
__device__ __forceinline__ unsigned f2ord(float x) {
    unsigned u = __float_as_uint(x);
    return (u & 0x80000000u) ? ~u : (u | 0x80000000u);
}
__device__ __forceinline__ float ord2f(unsigned o) {
    unsigned u = (o & 0x80000000u) ? (o & 0x7fffffffu) : ~o;
    return __uint_as_float(u);
}

__global__ __launch_bounds__(NN, 4)
void snn_kernel(const float* __restrict__ ic_g,     // [NN]
                const float* __restrict__ w,        // [NN, NN]
                const float* __restrict__ mu_g,     // [2]
                const float* __restrict__ v0_g,     // [NN]
                const float* __restrict__ i0_g,     // [NN]
                const float* __restrict__ s0_g,     // [NS, NN]
                const float* __restrict__ reset_s,  // [MAXSP, NS, NN]
                const int*   __restrict__ t1_p,     // scalar
                float* __restrict__ out_times,      // [NS, MAXSP]
                float* __restrict__ out_vals,       // [NS, MAXSP, NN, 3]
                float* __restrict__ out_marks)      // [NS, MAXSP, NN]
{
    const int smp = blockIdx.x;
    const int n   = threadIdx.x;
    const int warp = n >> 5, lane = n & 31;

    const float t1f = (float)(*t1_p);
    const float mu1 = mu_g[0];
    const float mu2 = mu_g[1];
    const float ic  = ic_g[n];

    float v = v0_g[n];
    float i = i0_g[n];
    float s = s0_g[(size_t)smp * NN + n];
    float t0 = 0.0f;

    __shared__ __align__(16) unsigned      bal[2][8];   // parity-buffered crossing ballots
    __shared__ unsigned long long          c_key[8];
    __shared__ float                       c_sp[8];

    int chk = 0;  // checked-step counter (block-uniform) -> ballot-buffer parity

    #pragma unroll 1
    for (int k = 0; k < MAXSP; k++) {
        const float rs = reset_s[((size_t)k * NS + smp) * NN + n];

        const float dt = (t1f - t0) * (1.0f / NSTEPS);
        bool  done = false;
        float tev  = t1f;
        bool  em   = false;
        int   eidx = 0;

        if (dt > 0.0f) {
            float t = t0;
            #pragma unroll 1
            for (int st = 0; st < NSTEPS; st++) {
                float vn, in_, sn;
                rk4_step(v, i, s, ic, mu1, mu2, dt, vn, in_, sn);

                // ---- fast path: block ANY via ballots, 1 barrier ----
                const unsigned cr = __ballot_sync(0xffffffffu, sn > 0.0f);
                const int p = chk & 1;
                chk++;
                if (lane == 0) bal[p][warp] = cr;
                __syncthreads();
                const uint4 a = *(const uint4*)&bal[p][0];
                const uint4 b = *(const uint4*)&bal[p][4];
                const unsigned any = a.x | a.y | a.z | a.w | b.x | b.y | b.z | b.w;

                if (any) {
                    // ---- trigger (once per round): argmax, 1 barrier ----
                    em = sn > 0.0f;

                    // eidx = first set bit in the already-synced ballot words
                    {
                        unsigned words[8] = {a.x, a.y, a.z, a.w, b.x, b.y, b.z, b.w};
                        #pragma unroll
                        for (int wv = 0; wv < 8; wv++) {
                            if (words[wv]) { eidx = wv * 32 + (__ffs(words[wv]) - 1); break; }
                        }
                    }

                    unsigned long long key =
                        ((unsigned long long)f2ord(sn) << 8) | (unsigned)(255 - n);
                    #pragma unroll
                    for (int off = 16; off; off >>= 1) {
                        unsigned long long ok = __shfl_xor_sync(0xffffffffu, key, off);
                        key = (ok > key) ? ok : key;
                    }
                    const int wl = ((int)(255 - (key & 0xffu))) & 31;  // winner lane
                    const float wsp = __shfl_sync(0xffffffffu, s, wl); // its s_prev
                    if (lane == 0) { c_key[warp] = key; c_sp[warp] = wsp; }
                    __syncthreads();

                    unsigned long long mkey = c_key[0]; float msp = c_sp[0];
                    #pragma unroll
                    for (int wv = 1; wv < 8; wv++)
                        if (c_key[wv] > mkey) { mkey = c_key[wv]; msp = c_sp[wv]; }
                    const float mval = ord2f((unsigned)(mkey >> 8));

                    float frac = msp / (msp - mval + 1e-12f);
                    frac = fminf(fmaxf(frac, 0.0f), 1.0f);
                    tev = t + frac * dt;
                    v += frac * (vn - v);
                    i += frac * (in_ - i);
                    s += frac * (sn - s);
                    done = true;
                    break;
                }
                v = vn; i = in_; s = sn;
                t += dt;
            }
        }

        // ---- outputs (pre-reset event state); tev = t1f if no trigger ----
        const size_t base = ((size_t)smp * MAXSP + k) * NN + n;
        if (n == 0) out_times[smp * MAXSP + k] = tev;
        out_vals[base * 3 + 0] = v;
        out_vals[base * 3 + 1] = i;
        out_vals[base * 3 + 2] = s;
        out_marks[base] = em ? 1.0f : 0.0f;

        // ---- reset & carry ----
        const float wr = done ? w[(size_t)eidx * NN + n] : 0.0f;
        v -= em ? V_RESET : 0.0f;
        i += wr;
        s  = fminf(em ? rs : s, 0.0f);
        t0 = tev;
    }
}

extern "C" void kernel_launch(void* const* d_in, const int* in_sizes, int n_in,
                              void* d_out, int out_size) {
    const float* ic      = (const float*)d_in[0];
    const float* w       = (const float*)d_in[1];
    const float* mu      = (const float*)d_in[2];
    const float* v0      = (const float*)d_in[3];
    const float* i0      = (const float*)d_in[4];
    const float* s0      = (const float*)d_in[5];
    const float* reset_s = (const float*)d_in[6];
    const int*   t1      = (const int*)d_in[7];

    float* out = (float*)d_out;
    float* out_times = out;                                    // NS*MAXSP
    float* out_vals  = out + (size_t)NS * MAXSP;               // NS*MAXSP*NN*3
    float* out_marks = out_vals + (size_t)NS * MAXSP * NN * 3; // NS*MAXSP*NN

    snn_kernel<<<NS, NN>>>(ic, w, mu, v0, i0, s0, reset_s, t1,
                           out_times, out_vals, out_marks);
}

// round 11
// speedup vs baseline: 3.0616x; 1.4084x over previous
#include <cuda_runtime.h>
#include <cuda_bf16.h>
#include <cstdint>

#define NN 256          // NUM_NEURONS
#define NS 512          // NUM_SAMPLES
#define MAXSP 32        // MAX_SPIKES (rounds)
#define NSTEPS 32       // RK4 steps per round
#define V_RESET 1.0f

__device__ __forceinline__ float sigm(float v) {
    const float e = __expf(-v);
    return __fdividef(1.0f, 1.0f + e);   // MUFU.EX2 + MUFU.RCP path
}

__device__ __forceinline__ void rk4_step(float v, float i, float s,
                                         float ic, float mu1, float mu2, float h,
                                         float& vn, float& in_, float& sn) {
    // k1
    float dv1 = mu1 * (i + ic - v);
    float di1 = -mu2 * i;
    float ds1 = sigm(v);
    // k2
    float v2 = fmaf(0.5f * h, dv1, v);
    float i2 = fmaf(0.5f * h, di1, i);
    float dv2 = mu1 * (i2 + ic - v2);
    float di2 = -mu2 * i2;
    float ds2 = sigm(v2);
    // k3
    float v3 = fmaf(0.5f * h, dv2, v);
    float i3 = fmaf(0.5f * h, di2, i);
    float dv3 = mu1 * (i3 + ic - v3);
    float di3 = -mu2 * i3;
    float ds3 = sigm(v3);
    // k4
    float v4 = fmaf(h, dv3, v);
    float i4 = fmaf(h, di3, i);
    float dv4 = mu1 * (i4 + ic - v4);
    float di4 = -mu2 * i4;
    float ds4 = sigm(v4);

    const float c = h * (1.0f / 6.0f);
    vn  = fmaf(c, dv1 + 2.0f * (dv2 + dv3) + dv4, v);
    in_ = fmaf(c, di1 + 2.0f * (di2 + di3) + di4, i);
    sn  = fmaf(c, ds1 + 2.0f * (ds2 + ds3) + ds4, s);
}

// order-preserving float<->uint maps
__device__ __forceinline__ unsigned f2ord(float x) {
    unsigned u = __float_as_uint(x);
    return (u & 0x80000000u) ? ~u : (u | 0x80000000u);
}
__device__ __forceinline__ float ord2f(unsigned o) {
    unsigned u = (o & 0x80000000u) ? (o & 0x7fffffffu) : ~o;
    return __uint_as_float(u);
}

__global__ __launch_bounds__(NN, 4)
void snn_kernel(const float* __restrict__ ic_g,     // [NN]
                const float* __restrict__ w,        // [NN, NN]
                const float* __restrict__ mu_g,     // [2]
                const float* __restrict__ v0_g,     // [NN]
                const float* __restrict__ i0_g,     // [NN]
                const float* __restrict__ s0_g,     // [NS, NN]
                const float* __restrict__ reset_s,  // [MAXSP, NS, NN]
                const int*   __restrict__ t1_p,     // scalar
                float* __restrict__ out_times,      // [NS, MAXSP]
                float* __restrict__ out_vals,       // [NS, MAXSP, NN, 3]
                float* __restrict__ out_marks)      // [NS, MAXSP, NN]
{
    const int smp = blockIdx.x;
    const int n   = threadIdx.x;

    const float t1f = (float)(*t1_p);
    const float mu1 = mu_g[0];
    const float mu2 = mu_g[1];
    const float ic  = ic_g[n];

    float v = v0_g[n];
    float i = i0_g[n];
    float s = s0_g[(size_t)smp * NN + n];
    float t0 = 0.0f;

    // parity-buffered trigger cells (0 == "no trigger": any crossing key has
    // top bit of ord(sn) set, so key >= 0x80000000_00 > 0)
    __shared__ unsigned long long key_sh[2];
    __shared__ int                eidx_sh[2];
    __shared__ float              s_all[NN];   // s_prev published by crossers

    if (n == 0) {
        key_sh[0] = key_sh[1] = 0ull;
        eidx_sh[0] = eidx_sh[1] = NN;
    }
    __syncthreads();

    #pragma unroll 1
    for (int k = 0; k < MAXSP; k++) {
        const float rs = reset_s[((size_t)k * NS + smp) * NN + n];

        const float dt = (t1f - t0) * (1.0f / NSTEPS);
        bool  done = false;
        float tev  = t1f;
        bool  em   = false;
        int   eidx = 0;

        if (dt > 0.0f) {
            #pragma unroll 1
            for (int st = 0; st < NSTEPS; st++) {
                float vn, in_, sn;
                rk4_step(v, i, s, ic, mu1, mu2, dt, vn, in_, sn);

                const int p = st & 1;
                const bool cross = sn > 0.0f;
                if (cross) {
                    // rare: publish candidacy (pre-barrier, few threads)
                    s_all[n] = s;
                    atomicMax(&key_sh[p],
                              ((unsigned long long)f2ord(sn) << 8)
                              | (unsigned long long)(255 - n));
                    atomicMin(&eidx_sh[p], n);
                }
                __syncthreads();
                const unsigned long long key = key_sh[p];

                if (key) {
                    // ---- trigger (once per round), block-uniform ----
                    em   = cross;
                    eidx = eidx_sh[p];
                    const int   widx = 255 - (int)(key & 0xffull);
                    const float mval = ord2f((unsigned)(key >> 8));
                    const float msp  = s_all[widx];

                    float frac = msp / (msp - mval + 1e-12f);
                    frac = fminf(fmaxf(frac, 0.0f), 1.0f);
                    tev = t0 + (float)st * dt + frac * dt;
                    v += frac * (vn - v);
                    i += frac * (in_ - i);
                    s += frac * (sn - s);
                    done = true;

                    __syncthreads();          // all reads of cells complete
                    if (n == 0) { key_sh[p] = 0ull; eidx_sh[p] = NN; }
                    // next barrier (next round's first step) orders this
                    // reset before any subsequent read/write of cell p.
                    break;
                }
                v = vn; i = in_; s = sn;
            }
        }

        // ---- outputs (pre-reset event state); tev = t1f if no trigger ----
        const size_t base = ((size_t)smp * MAXSP + k) * NN + n;
        if (n == 0) out_times[smp * MAXSP + k] = tev;
        out_vals[base * 3 + 0] = v;
        out_vals[base * 3 + 1] = i;
        out_vals[base * 3 + 2] = s;
        out_marks[base] = em ? 1.0f : 0.0f;

        // ---- reset & carry ----
        const float wr = done ? w[(size_t)eidx * NN + n] : 0.0f;
        v -= em ? V_RESET : 0.0f;
        i += wr;
        s  = fminf(em ? rs : s, 0.0f);
        t0 = tev;
    }
}

extern "C" void kernel_launch(void* const* d_in, const int* in_sizes, int n_in,
                              void* d_out, int out_size) {
    const float* ic      = (const float*)d_in[0];
    const float* w       = (const float*)d_in[1];
    const float* mu      = (const float*)d_in[2];
    const float* v0      = (const float*)d_in[3];
    const float* i0      = (const float*)d_in[4];
    const float* s0      = (const float*)d_in[5];
    const float* reset_s = (const float*)d_in[6];
    const int*   t1      = (const int*)d_in[7];

    float* out = (float*)d_out;
    float* out_times = out;                                    // NS*MAXSP
    float* out_vals  = out + (size_t)NS * MAXSP;               // NS*MAXSP*NN*3
    float* out_marks = out_vals + (size_t)NS * MAXSP * NN * 3; // NS*MAXSP*NN

    snn_kernel<<<NS, NN>>>(ic, w, mu, v0, i0, s0, reset_s, t1,
                           out_times, out_vals, out_marks);
}